// round 2
// baseline (speedup 1.0000x reference)
#include <cuda_runtime.h>
#include <cstdint>
#include <cstddef>

// Problem constants
#define E_LOC   8
#define B_DIM   4
#define C_CAP   1024
#define D_MODEL 1024
#define D_FF    4096

// 512 MB scratch for the hidden activations [B, E, C, F] fp32.
// Static __device__ array: allocated at module load (allowed; no runtime alloc).
__device__ float g_hidden[(size_t)B_DIM * E_LOC * C_CAP * D_FF];

__device__ __forceinline__ uint32_t f2tf(float x) {
    uint32_t u;
    asm("cvt.rna.tf32.f32 %0, %1;" : "=r"(u) : "f"(x));
    return u;
}

__device__ __forceinline__ float gelu_exact(float x) {
    return 0.5f * x * (1.0f + erff(x * 0.7071067811865476f));
}

// NT GEMM: C[M,N] = A[M,K] @ B[N,K]^T (+bias[N]) (+optional exact GELU)
// A row-major (lda), B row-major (ldb) = weights [N_out, K_in], C row-major (ldc).
// blockIdx.z = b*E + e. A/C stride by z; B/bias stride by expert (z % E).
// Tiles: BM=BN=128, BK=32. 256 threads = 8 warps in a 4(M) x 2(N) grid;
// warp tile 32x64 = 2x8 fragments of m16n8k8 tf32.
template <bool GELU>
__global__ __launch_bounds__(256)
void gemm_nt_tf32(const float* __restrict__ A,
                  const float* __restrict__ Bw,
                  const float* __restrict__ bias,
                  float* __restrict__ C,
                  int K, int lda, int ldb, int ldc,
                  size_t a_zstr, size_t b_estr, int bias_n, size_t c_zstr)
{
    // Padded smem: row stride 36 floats -> conflict-free quad-pattern LDS
    __shared__ float As[128 * 36];
    __shared__ float Bs[128 * 36];

    const int tid  = threadIdx.x;
    const int lane = tid & 31;
    const int warp = tid >> 5;
    const int wm   = warp & 3;   // warp row (M), 0..3 -> rows wm*32
    const int wn   = warp >> 2;  // warp col (N), 0..1 -> cols wn*64

    const int z = blockIdx.z;
    const int e = z & (E_LOC - 1);

    const float* Ab    = A    + (size_t)z * a_zstr + (size_t)blockIdx.y * 128 * lda;
    const float* Bb    = Bw   + (size_t)e * b_estr + (size_t)blockIdx.x * 128 * ldb;
    const float* biasb = bias + (size_t)e * bias_n + (size_t)blockIdx.x * 128;
    float*       Cb    = C    + (size_t)z * c_zstr + (size_t)blockIdx.y * 128 * ldc
                              + (size_t)blockIdx.x * 128;

    // Per-thread gmem->smem mapping: 1024 float4 slots per tile, 4 per thread.
    int arow[4], ac4[4];
#pragma unroll
    for (int i = 0; i < 4; i++) {
        int idx = i * 256 + tid;
        arow[i] = idx >> 3;        // 0..127
        ac4[i]  = (idx & 7) * 4;   // 0,4,...,28
    }

    float4 ra[4], rb[4];
    float acc[2][8][4];
#pragma unroll
    for (int mt = 0; mt < 2; mt++)
#pragma unroll
        for (int nt = 0; nt < 8; nt++)
#pragma unroll
            for (int i = 0; i < 4; i++) acc[mt][nt][i] = 0.0f;

    const int NIT = K >> 5;

    // Load tile 0
#pragma unroll
    for (int i = 0; i < 4; i++) {
        ra[i] = *reinterpret_cast<const float4*>(Ab + (size_t)arow[i] * lda + ac4[i]);
        rb[i] = *reinterpret_cast<const float4*>(Bb + (size_t)arow[i] * ldb + ac4[i]);
    }
#pragma unroll
    for (int i = 0; i < 4; i++) {
        *reinterpret_cast<float4*>(&As[arow[i] * 36 + ac4[i]]) = ra[i];
        *reinterpret_cast<float4*>(&Bs[arow[i] * 36 + ac4[i]]) = rb[i];
    }
    __syncthreads();

    for (int kt = 0; kt < NIT; ++kt) {
        // Prefetch next gmem tile into registers
        if (kt + 1 < NIT) {
            const int koff = (kt + 1) * 32;
#pragma unroll
            for (int i = 0; i < 4; i++) {
                ra[i] = *reinterpret_cast<const float4*>(Ab + (size_t)arow[i] * lda + koff + ac4[i]);
                rb[i] = *reinterpret_cast<const float4*>(Bb + (size_t)arow[i] * ldb + koff + ac4[i]);
            }
        }

#pragma unroll
        for (int kk = 0; kk < 4; kk++) {
            const int k0 = kk * 8;
            uint32_t af[2][4];
#pragma unroll
            for (int mt = 0; mt < 2; mt++) {
                const int ar = wm * 32 + mt * 16 + (lane >> 2);
                const int ac = k0 + (lane & 3);
                af[mt][0] = f2tf(As[ar * 36 + ac]);
                af[mt][1] = f2tf(As[(ar + 8) * 36 + ac]);
                af[mt][2] = f2tf(As[ar * 36 + ac + 4]);
                af[mt][3] = f2tf(As[(ar + 8) * 36 + ac + 4]);
            }
            uint32_t bf[8][2];
#pragma unroll
            for (int nt = 0; nt < 8; nt++) {
                const int br = wn * 64 + nt * 8 + (lane >> 2);
                const int bc = k0 + (lane & 3);
                bf[nt][0] = f2tf(Bs[br * 36 + bc]);
                bf[nt][1] = f2tf(Bs[br * 36 + bc + 4]);
            }
#pragma unroll
            for (int mt = 0; mt < 2; mt++)
#pragma unroll
                for (int nt = 0; nt < 8; nt++) {
                    asm volatile(
                        "mma.sync.aligned.m16n8k8.row.col.f32.tf32.tf32.f32 "
                        "{%0,%1,%2,%3},{%4,%5,%6,%7},{%8,%9},{%0,%1,%2,%3};"
                        : "+f"(acc[mt][nt][0]), "+f"(acc[mt][nt][1]),
                          "+f"(acc[mt][nt][2]), "+f"(acc[mt][nt][3])
                        : "r"(af[mt][0]), "r"(af[mt][1]), "r"(af[mt][2]), "r"(af[mt][3]),
                          "r"(bf[nt][0]), "r"(bf[nt][1]));
                }
        }

        __syncthreads();
        if (kt + 1 < NIT) {
#pragma unroll
            for (int i = 0; i < 4; i++) {
                *reinterpret_cast<float4*>(&As[arow[i] * 36 + ac4[i]]) = ra[i];
                *reinterpret_cast<float4*>(&Bs[arow[i] * 36 + ac4[i]]) = rb[i];
            }
            __syncthreads();
        }
    }

    // Epilogue: bias (+ exact GELU), write fp32
#pragma unroll
    for (int mt = 0; mt < 2; mt++) {
        const int r0 = wm * 32 + mt * 16 + (lane >> 2);
#pragma unroll
        for (int nt = 0; nt < 8; nt++) {
            const int c0 = wn * 64 + nt * 8 + 2 * (lane & 3);
            const float b0 = biasb[c0];
            const float b1 = biasb[c0 + 1];
            float v0 = acc[mt][nt][0] + b0;
            float v1 = acc[mt][nt][1] + b1;
            float v2 = acc[mt][nt][2] + b0;
            float v3 = acc[mt][nt][3] + b1;
            if (GELU) {
                v0 = gelu_exact(v0);
                v1 = gelu_exact(v1);
                v2 = gelu_exact(v2);
                v3 = gelu_exact(v3);
            }
            *reinterpret_cast<float2*>(Cb + (size_t)r0 * ldc + c0)       = make_float2(v0, v1);
            *reinterpret_cast<float2*>(Cb + (size_t)(r0 + 8) * ldc + c0) = make_float2(v2, v3);
        }
    }
}

extern "C" void kernel_launch(void* const* d_in, const int* in_sizes, int n_in,
                              void* d_out, int out_size)
{
    const float* x  = (const float*)d_in[0];  // [B, E*C, D]
    const float* w1 = (const float*)d_in[1];  // [E, F, D]
    const float* b1 = (const float*)d_in[2];  // [E, F]
    const float* w2 = (const float*)d_in[3];  // [E, D, F]
    const float* b2 = (const float*)d_in[4];  // [E, D]
    float* out = (float*)d_out;               // [B, E*C, D]

    float* h = nullptr;
    cudaGetSymbolAddress((void**)&h, g_hidden);  // metadata query only; capture-safe

    const int ZB = B_DIM * E_LOC;  // 32 (b,e) blocks

    // GEMM1: h = gelu(x @ w1^T + b1)   M=C=1024, N=F=4096, K=D=1024
    {
        dim3 grid(D_FF / 128, C_CAP / 128, ZB);
        gemm_nt_tf32<true><<<grid, 256>>>(
            x, w1, b1, h,
            /*K=*/D_MODEL, /*lda=*/D_MODEL, /*ldb=*/D_MODEL, /*ldc=*/D_FF,
            /*a_zstr=*/(size_t)C_CAP * D_MODEL,
            /*b_estr=*/(size_t)D_FF * D_MODEL,
            /*bias_n=*/D_FF,
            /*c_zstr=*/(size_t)C_CAP * D_FF);
    }

    // GEMM2: y = h @ w2^T + b2          M=C=1024, N=D=1024, K=F=4096
    {
        dim3 grid(D_MODEL / 128, C_CAP / 128, ZB);
        gemm_nt_tf32<false><<<grid, 256>>>(
            h, w2, b2, out,
            /*K=*/D_FF, /*lda=*/D_FF, /*ldb=*/D_FF, /*ldc=*/D_MODEL,
            /*a_zstr=*/(size_t)C_CAP * D_FF,
            /*b_estr=*/(size_t)D_MODEL * D_FF,
            /*bias_n=*/D_MODEL,
            /*c_zstr=*/(size_t)C_CAP * D_MODEL);
    }
}

// round 9
// speedup vs baseline: 1.2102x; 1.2102x over previous
#include <cuda_runtime.h>
#include <cstdint>
#include <cstddef>

// ---------------- problem constants ----------------
#define E_LOC   8
#define B_DIM   4
#define C_CAP   1024
#define D_MODEL 1024
#define D_FF    4096

// ---------------- tile config ----------------
// Block tile 128(M) x 256(N) x 32(K), 256 threads = 8 warps in 2(M) x 4(N),
// warp tile 64x64 = 4x8 fragments of mma.sync.m16n8k8.tf32. 3-stage cp.async.
#define BM 128
#define BN 256
#define BK 32
#define STAGES 3

#define PAD_LD      36                      // floats per row (32 data + 4 pad)
#define A_FLOATS    (BM * PAD_LD)           // 4608
#define B_FLOATS    (BN * PAD_LD)           // 9216
#define STG_FLOATS  (A_FLOATS + B_FLOATS)   // 13824
#define SMEM_BYTES  (STAGES * STG_FLOATS * 4)   // 165888

// ---------------- scratch (static __device__: no runtime alloc) ----------------
__device__ float g_hidden[(size_t)B_DIM * E_LOC * C_CAP * D_FF];   // 512 MB
__device__ float g_xr [(size_t)B_DIM * E_LOC * C_CAP * D_MODEL];   // 128 MB
__device__ float g_w1r[(size_t)E_LOC * D_FF * D_MODEL];            // 128 MB
__device__ float g_w2r[(size_t)E_LOC * D_MODEL * D_FF];            // 128 MB

// ---------------- helpers ----------------
__device__ __forceinline__ float rna_tf32(float x) {
    uint32_t u;
    asm("cvt.rna.tf32.f32 %0, %1;" : "=r"(u) : "f"(x));
    return __uint_as_float(u);
}
__device__ __forceinline__ uint32_t smem_u32(const void* p) {
    uint32_t a;
    asm("{ .reg .u64 t; cvta.to.shared.u64 t, %1; cvt.u32.u64 %0, t; }" : "=r"(a) : "l"(p));
    return a;
}
__device__ __forceinline__ void cp_async16(uint32_t saddr, const void* g) {
    asm volatile("cp.async.cg.shared.global [%0], [%1], 16;" :: "r"(saddr), "l"(g));
}
#define CP_COMMIT() asm volatile("cp.async.commit_group;" ::: "memory")
#define CP_WAIT1()  asm volatile("cp.async.wait_group 1;" ::: "memory")

__device__ __forceinline__ float gelu_exact(float x) {
    return 0.5f * x * (1.0f + erff(x * 0.7071067811865476f));
}

// ---------------- stage loader: gmem -> padded smem via cp.async ----------------
// A: 128 rows x 32 floats (8x16B chunks/row); B: 256 rows x 32 floats.
__device__ __forceinline__ void load_stage(uint32_t sbase, int buf, int kt,
                                           const float* __restrict__ Ab,
                                           const float* __restrict__ Bb,
                                           int K, int tid)
{
    const int k0 = kt * BK;
    const uint32_t abase = sbase + (uint32_t)buf * (STG_FLOATS * 4);
    const uint32_t bbase = abase + A_FLOATS * 4;
#pragma unroll
    for (int i = 0; i < 4; i++) {               // 1024 A-chunks / 256 threads
        int idx = i * 256 + tid;
        int r = idx >> 3, j = idx & 7;
        cp_async16(abase + r * (PAD_LD * 4) + j * 16, Ab + (size_t)r * K + k0 + j * 4);
    }
#pragma unroll
    for (int i = 0; i < 8; i++) {               // 2048 B-chunks / 256 threads
        int idx = i * 256 + tid;
        int r = idx >> 3, j = idx & 7;
        cp_async16(bbase + r * (PAD_LD * 4) + j * 16, Bb + (size_t)r * K + k0 + j * 4);
    }
}

// ---------------- grouped NT GEMM: C = A @ B^T (+bias)(+GELU) -----------------
// Inputs MUST already be tf32-representable (rna-pre-rounded): the mainloop
// feeds raw f32 bits to mma.sync.tf32 with no per-element cvt.
template <bool GELU>
__global__ __launch_bounds__(256, 1)
void gemm_nt_tf32(const float* __restrict__ A, const float* __restrict__ Bw,
                  const float* __restrict__ bias, float* __restrict__ C,
                  int K, int ldc, size_t a_zstr, size_t b_estr, int bias_n, size_t c_zstr)
{
    extern __shared__ float smem[];
    const uint32_t sbase = smem_u32(smem);

    const int tid  = threadIdx.x;
    const int lane = tid & 31;
    const int warp = tid >> 5;
    const int wm   = warp >> 2;   // 0..1 -> rows wm*64
    const int wn   = warp & 3;    // 0..3 -> cols wn*64

    const int z = blockIdx.z;
    const int e = z & (E_LOC - 1);

    const float* Ab    = A    + (size_t)z * a_zstr + (size_t)blockIdx.y * BM * K;
    const float* Bb    = Bw   + (size_t)e * b_estr + (size_t)blockIdx.x * BN * K;
    const float* biasb = bias + (size_t)e * bias_n + (size_t)blockIdx.x * BN;
    float*       Cb    = C    + (size_t)z * c_zstr + (size_t)blockIdx.y * BM * ldc
                              + (size_t)blockIdx.x * BN;

    float acc[4][8][4];
#pragma unroll
    for (int mt = 0; mt < 4; mt++)
#pragma unroll
        for (int nt = 0; nt < 8; nt++)
#pragma unroll
            for (int i = 0; i < 4; i++) acc[mt][nt][i] = 0.0f;

    const int NK = K >> 5;

    // prologue: stages 0,1
    load_stage(sbase, 0, 0, Ab, Bb, K, tid); CP_COMMIT();
    load_stage(sbase, 1, 1, Ab, Bb, K, tid); CP_COMMIT();

#pragma unroll 1
    for (int kt = 0; kt < NK; ++kt) {
        CP_WAIT1();                 // stage kt resident (one empty/real group may be in flight)
        __syncthreads();            // all warps done reading buffer (kt+2)%3 (read at kt-1)

        // prefetch stage kt+2 (empty commit keeps group accounting uniform)
        if (kt + 2 < NK) {
            int buf = kt + 2; buf -= (buf >= 3) ? 3 : 0; buf -= (buf >= 3) ? 3 : 0;
            load_stage(sbase, (kt + 2) % 3, kt + 2, Ab, Bb, K, tid);
        }
        CP_COMMIT();

        const float* As = smem + (kt % 3) * STG_FLOATS;
        const float* Bs = As + A_FLOATS;

#pragma unroll
        for (int kk = 0; kk < 4; kk++) {
            const int c  = kk * 8 + (lane & 3);
            uint32_t af[4][4];
#pragma unroll
            for (int mt = 0; mt < 4; mt++) {
                const int r = wm * 64 + mt * 16 + (lane >> 2);
                af[mt][0] = __float_as_uint(As[r * PAD_LD + c]);
                af[mt][1] = __float_as_uint(As[(r + 8) * PAD_LD + c]);
                af[mt][2] = __float_as_uint(As[r * PAD_LD + c + 4]);
                af[mt][3] = __float_as_uint(As[(r + 8) * PAD_LD + c + 4]);
            }
            uint32_t bf[8][2];
#pragma unroll
            for (int nt = 0; nt < 8; nt++) {
                const int r = wn * 64 + nt * 8 + (lane >> 2);
                bf[nt][0] = __float_as_uint(Bs[r * PAD_LD + c]);
                bf[nt][1] = __float_as_uint(Bs[r * PAD_LD + c + 4]);
            }
#pragma unroll
            for (int mt = 0; mt < 4; mt++)
#pragma unroll
                for (int nt = 0; nt < 8; nt++) {
                    asm volatile(
                        "mma.sync.aligned.m16n8k8.row.col.f32.tf32.tf32.f32 "
                        "{%0,%1,%2,%3},{%4,%5,%6,%7},{%8,%9},{%0,%1,%2,%3};"
                        : "+f"(acc[mt][nt][0]), "+f"(acc[mt][nt][1]),
                          "+f"(acc[mt][nt][2]), "+f"(acc[mt][nt][3])
                        : "r"(af[mt][0]), "r"(af[mt][1]), "r"(af[mt][2]), "r"(af[mt][3]),
                          "r"(bf[nt][0]), "r"(bf[nt][1]));
                }
        }
    }

    // ---------------- epilogue: bias (+GELU, rna-rounded for GEMM2 input) ----------------
#pragma unroll
    for (int mt = 0; mt < 4; mt++) {
        const int r0 = wm * 64 + mt * 16 + (lane >> 2);
#pragma unroll
        for (int nt = 0; nt < 8; nt++) {
            const int c0 = wn * 64 + nt * 8 + 2 * (lane & 3);
            const float b0 = biasb[c0];
            const float b1 = biasb[c0 + 1];
            float v0 = acc[mt][nt][0] + b0;
            float v1 = acc[mt][nt][1] + b1;
            float v2 = acc[mt][nt][2] + b0;
            float v3 = acc[mt][nt][3] + b1;
            if (GELU) {
                v0 = rna_tf32(gelu_exact(v0));
                v1 = rna_tf32(gelu_exact(v1));
                v2 = rna_tf32(gelu_exact(v2));
                v3 = rna_tf32(gelu_exact(v3));
            }
            *reinterpret_cast<float2*>(Cb + (size_t)r0 * ldc + c0)       = make_float2(v0, v1);
            *reinterpret_cast<float2*>(Cb + (size_t)(r0 + 8) * ldc + c0) = make_float2(v2, v3);
        }
    }
}

// ---------------- prepass: rna-round fp32 -> tf32-representable fp32 ----------------
__global__ void rna_round_kernel(const float4* __restrict__ in, float4* __restrict__ out,
                                 size_t n4)
{
    size_t i = (size_t)blockIdx.x * blockDim.x + threadIdx.x;
    const size_t stride = (size_t)gridDim.x * blockDim.x;
    for (; i < n4; i += stride) {
        float4 v = in[i];
        v.x = rna_tf32(v.x); v.y = rna_tf32(v.y);
        v.z = rna_tf32(v.z); v.w = rna_tf32(v.w);
        out[i] = v;
    }
}

// ---------------- launch ----------------
extern "C" void kernel_launch(void* const* d_in, const int* in_sizes, int n_in,
                              void* d_out, int out_size)
{
    const float* x  = (const float*)d_in[0];  // [B, E*C, D]
    const float* w1 = (const float*)d_in[1];  // [E, F, D]
    const float* b1 = (const float*)d_in[2];  // [E, F]
    const float* w2 = (const float*)d_in[3];  // [E, D, F]
    const float* b2 = (const float*)d_in[4];  // [E, D]
    float* out = (float*)d_out;               // [B, E*C, D]

    float *h, *xr, *w1r, *w2r;
    cudaGetSymbolAddress((void**)&h,   g_hidden);
    cudaGetSymbolAddress((void**)&xr,  g_xr);
    cudaGetSymbolAddress((void**)&w1r, g_w1r);
    cudaGetSymbolAddress((void**)&w2r, g_w2r);

    cudaFuncSetAttribute(gemm_nt_tf32<true>,  cudaFuncAttributeMaxDynamicSharedMemorySize, SMEM_BYTES);
    cudaFuncSetAttribute(gemm_nt_tf32<false>, cudaFuncAttributeMaxDynamicSharedMemorySize, SMEM_BYTES);

    const size_t nx = (size_t)B_DIM * E_LOC * C_CAP * D_MODEL;  // 32M
    const size_t nw = (size_t)E_LOC * D_FF * D_MODEL;           // 32M
    rna_round_kernel<<<2048, 256>>>((const float4*)x,  (float4*)xr,  nx / 4);
    rna_round_kernel<<<2048, 256>>>((const float4*)w1, (float4*)w1r, nw / 4);
    rna_round_kernel<<<2048, 256>>>((const float4*)w2, (float4*)w2r, nw / 4);

    const int ZB = B_DIM * E_LOC;  // 32

    // GEMM1: hidden = gelu_rna(x @ w1^T + b1)   M=1024, N=4096, K=1024
    {
        dim3 grid(D_FF / BN, C_CAP / BM, ZB);   // (16, 8, 32)
        gemm_nt_tf32<true><<<grid, 256, SMEM_BYTES>>>(
            xr, w1r, b1, h,
            /*K=*/D_MODEL, /*ldc=*/D_FF,
            /*a_zstr=*/(size_t)C_CAP * D_MODEL,
            /*b_estr=*/(size_t)D_FF * D_MODEL,
            /*bias_n=*/D_FF,
            /*c_zstr=*/(size_t)C_CAP * D_FF);
    }

    // GEMM2: out = hidden @ w2^T + b2           M=1024, N=1024, K=4096
    {
        dim3 grid(D_MODEL / BN, C_CAP / BM, ZB);  // (4, 8, 32)
        gemm_nt_tf32<false><<<grid, 256, SMEM_BYTES>>>(
            h, w2r, b2, out,
            /*K=*/D_FF, /*ldc=*/D_MODEL,
            /*a_zstr=*/(size_t)C_CAP * D_FF,
            /*b_estr=*/(size_t)D_MODEL * D_FF,
            /*bias_n=*/D_MODEL,
            /*c_zstr=*/(size_t)C_CAP * D_MODEL);
    }
}